// round 16
// baseline (speedup 1.0000x reference)
#include <cuda_runtime.h>
#include <cuda_fp16.h>
#include <stdint.h>

// ---------------------------------------------------------------------------
// Problem constants: B=4, S=4096, D=128, DA=64
// ---------------------------------------------------------------------------
#define B_DIM 4
#define S_DIM 4096
#define D_VAL 128
#define D_ATT 64
#define ROWS_TOTAL (B_DIM * S_DIM)   // 16384

// fp16 scratch (device globals: allocation-free per harness rules).
// Q never goes through global: proj block i's rows ARE fa block i's q-rows,
// so Q fragments are written straight into SMEM.
__device__ __align__(128) __half g_Kh[ROWS_TOTAL * D_ATT];
__device__ __align__(128) __half g_Vh[(size_t)ROWS_TOTAL * D_VAL];
__device__ unsigned int g_bar;   // epoch barrier counter (monotonic across replays)

// ---------------------------------------------------------------------------
// Small PTX helpers
// ---------------------------------------------------------------------------
#define CP_ASYNC16(dst, src) \
    asm volatile("cp.async.cg.shared.global [%0], [%1], 16;" \
                 :: "r"(dst), "l"(src) : "memory")
#define CP_COMMIT() asm volatile("cp.async.commit_group;" ::: "memory")
#define CP_WAIT(n)  asm volatile("cp.async.wait_group %0;" :: "n"(n) : "memory")

__device__ __forceinline__ uint32_t pack_f16x2(float f0, float f1) {
    // low 16 bits = f16(f0), high 16 bits = f16(f1)
    uint32_t r;
    asm("cvt.rn.f16x2.f32 %0, %1, %2;" : "=r"(r) : "f"(f1), "f"(f0));
    return r;
}

__device__ __forceinline__ uint32_t ex2_f16x2(uint32_t s) {
    uint32_t r;
    asm("ex2.approx.f16x2 %0, %1;" : "=r"(r) : "r"(s));
    return r;
}

__device__ __forceinline__ uint32_t s2u(const void* p) {
    uint32_t a;
    asm("{ .reg .u64 t; cvta.to.shared.u64 t, %1; cvt.u32.u64 %0, t; }"
        : "=r"(a) : "l"(p));
    return a;
}

__device__ __forceinline__ void ldsm_x4(uint32_t (&r)[4], uint32_t addr) {
    asm volatile("ldmatrix.sync.aligned.m8n8.x4.shared.b16 {%0,%1,%2,%3}, [%4];"
                 : "=r"(r[0]), "=r"(r[1]), "=r"(r[2]), "=r"(r[3]) : "r"(addr));
}
__device__ __forceinline__ void ldsm_x4_t(uint32_t (&r)[4], uint32_t addr) {
    asm volatile("ldmatrix.sync.aligned.m8n8.x4.trans.shared.b16 {%0,%1,%2,%3}, [%4];"
                 : "=r"(r[0]), "=r"(r[1]), "=r"(r[2]), "=r"(r[3]) : "r"(addr));
}

__device__ __forceinline__ void mma_f16(float (&c)[4], const uint32_t (&a)[4],
                                        uint32_t b0, uint32_t b1) {
    asm volatile(
        "mma.sync.aligned.m16n8k16.row.col.f32.f16.f16.f32 "
        "{%0,%1,%2,%3},{%4,%5,%6,%7},{%8,%9},{%0,%1,%2,%3};"
        : "+f"(c[0]), "+f"(c[1]), "+f"(c[2]), "+f"(c[3])
        : "r"(a[0]), "r"(a[1]), "r"(a[2]), "r"(a[3]), "r"(b0), "r"(b1));
}

// ---------------------------------------------------------------------------
// SMEM overlay (time-multiplexed, separated by the device barrier):
//   proj phase: PX (x fp16)  [0, 34816) ; W bufs [34816, 69632)
//   fa phase:   SQH          [0, 18432) ; K bufs [18432, 36864) ; V [36864, 71680)
// Q fragments are STS'd into SQH during proj chunk 0's epilogue — legal
// because the PX region is dead once the A fragments are in registers.
// ---------------------------------------------------------------------------
#define PX_H  0
#define PWBUF 34816
#define PW_BUF_SZ 17408
#define SQH   0
#define SKBUF 18432
#define K_BUF_SZ 9216
#define SVBUF 36864
#define V_BUF_SZ 17408
#define SMEM_TOTAL 71680

__global__ void __launch_bounds__(256, 1) fused_kernel(
    const float* __restrict__ x,
    const float* __restrict__ Wq,
    const float* __restrict__ Wk,
    const float* __restrict__ Wv,
    float* __restrict__ out)
{
    extern __shared__ char smc[];
    const uint32_t sb = s2u(smc);
    const int tid  = threadIdx.x;
    const int wid  = tid >> 5;
    const int lane = tid & 31;
    const int row0 = blockIdx.x * 128;     // proj rows == fa q-rows
    const int g  = lane >> 2;
    const int t4 = lane & 3;

    // =======================================================================
    // Phase 1: QKV projection (R15 proj, Q epilogue redirected to SMEM)
    // =======================================================================
    {
        const float* const wsrc[4] = {Wq, Wk, Wv, Wv + 64 * D_VAL};

        // issue W chunk 0 fp32 loads (latency hidden by x staging)
        float4 wr[8];
        #pragma unroll
        for (int i = 0; i < 8; i++) {
            int u = tid + i * 256;
            wr[i] = *(const float4*)(wsrc[0] + (size_t)(u >> 5) * D_VAL + (u & 31) * 4);
        }

        // stage x tile: fp32 -> fp16 into SMEM
        #pragma unroll
        for (int i = 0; i < 16; i++) {
            int f4 = tid + i * 256;                    // 4096 float4 = 128x128
            int row = f4 >> 5, c4 = f4 & 31;
            float4 v = *(const float4*)(x + (size_t)(row0 + row) * D_VAL + c4 * 4);
            uint32_t h01 = pack_f16x2(v.x, v.y);
            uint32_t h23 = pack_f16x2(v.z, v.w);
            *(uint2*)(smc + PX_H + row * 272 + c4 * 8) = make_uint2(h01, h23);
        }

        // convert + store W chunk 0 into buffer 0
        #pragma unroll
        for (int i = 0; i < 8; i++) {
            int u = tid + i * 256;
            int row = u >> 5, c4 = u & 31;
            uint32_t h01 = pack_f16x2(wr[i].x, wr[i].y);
            uint32_t h23 = pack_f16x2(wr[i].z, wr[i].w);
            *(uint2*)(smc + PWBUF + row * 272 + c4 * 8) = make_uint2(h01, h23);
        }
        __syncthreads();

        // A fragments (persistent): 8 k-steps
        uint32_t ah[8][4];
        {
            const int rowq = wid * 16 + (lane & 15);
            const int colh = (lane >> 4) * 8;
            #pragma unroll
            for (int ks = 0; ks < 8; ks++)
                ldsm_x4(ah[ks], sb + PX_H + rowq * 272 + (ks * 16 + colh) * 2);
        }

        const int krow = lane & 7;
        const int kq   = (lane >> 3) & 3;

        #pragma unroll 1
        for (int c = 0; c < 4; c++) {
            const int buf = c & 1;

            if (c < 3) {
                #pragma unroll
                for (int i = 0; i < 8; i++) {
                    int u = tid + i * 256;
                    wr[i] = *(const float4*)(wsrc[c + 1]
                              + (size_t)(u >> 5) * D_VAL + (u & 31) * 4);
                }
            }

            const uint32_t wb = sb + PWBUF + buf * PW_BUF_SZ;

            float C[8][4];
            #pragma unroll
            for (int i = 0; i < 8; i++)
                #pragma unroll
                for (int j = 0; j < 4; j++) C[i][j] = 0.f;

            #pragma unroll
            for (int kp = 0; kp < 4; kp++) {
                #pragma unroll
                for (int nt = 0; nt < 8; nt++) {
                    uint32_t a = wb + (nt * 8 + krow) * 272 + (kp * 32 + kq * 8) * 2;
                    uint32_t bh[4];
                    ldsm_x4(bh, a);
                    mma_f16(C[nt], ah[2 * kp],     bh[0], bh[1]);
                    mma_f16(C[nt], ah[2 * kp + 1], bh[2], bh[3]);
                }
            }

            if (c == 0) {
                // Q: scale by 0.125*log2(e), STS straight into fa's SQH
                // layout (row*144 + col*2). PX region is dead (ah in regs).
                const float sc = 0.18033688f;
                const int rl = wid * 16 + g;           // local q-row
                #pragma unroll
                for (int nt = 0; nt < 8; nt++) {
                    const int cb = (nt * 8 + t4 * 2) * 2;   // col byte offset
                    *(uint32_t*)(smc + SQH + rl * 144 + cb) =
                        pack_f16x2(C[nt][0] * sc, C[nt][1] * sc);
                    *(uint32_t*)(smc + SQH + (rl + 8) * 144 + cb) =
                        pack_f16x2(C[nt][2] * sc, C[nt][3] * sc);
                }
            } else {
                __half* dst;
                int ldd, col0;
                if (c == 1) { dst = g_Kh; ldd = D_ATT; col0 = 0; }
                else        { dst = g_Vh; ldd = D_VAL; col0 = (c - 2) * 64; }
                const int r0 = row0 + wid * 16 + g;
                #pragma unroll
                for (int nt = 0; nt < 8; nt++) {
                    const int cc = col0 + nt * 8 + t4 * 2;
                    *(uint32_t*)(dst + (size_t)r0 * ldd + cc) =
                        pack_f16x2(C[nt][0], C[nt][1]);
                    *(uint32_t*)(dst + (size_t)(r0 + 8) * ldd + cc) =
                        pack_f16x2(C[nt][2], C[nt][3]);
                }
            }

            if (c < 3) {
                const uint32_t db = PWBUF + (buf ^ 1) * PW_BUF_SZ;
                #pragma unroll
                for (int i = 0; i < 8; i++) {
                    int u = tid + i * 256;
                    int row = u >> 5, c4 = u & 31;
                    uint32_t h01 = pack_f16x2(wr[i].x, wr[i].y);
                    uint32_t h23 = pack_f16x2(wr[i].z, wr[i].w);
                    *(uint2*)(smc + db + row * 272 + c4 * 8) = make_uint2(h01, h23);
                }
                __syncthreads();
            }
        }
    }

    // =======================================================================
    // Device-wide epoch barrier: all K/V STGs visible before any CTA reads.
    // Each launch contributes exactly 128 arrivals -> replay-safe targets.
    // 128 CTAs on 148 SMs: all resident, spin cannot deadlock.
    // =======================================================================
    __threadfence();
    __syncthreads();
    if (tid == 0) {
        unsigned int arrive = atomicAdd(&g_bar, 1u);
        unsigned int target = (arrive & ~127u) + 128u;
        while (*(volatile unsigned int*)&g_bar < target) { }
        __threadfence();
    }
    __syncthreads();

    // =======================================================================
    // Phase 2: flash attention (R15 fa, minus the Q staging — Q is in SQH)
    // =======================================================================
    const int b  = blockIdx.x >> 5;
    const int qt = blockIdx.x & 31;
    const int qrow0 = b * S_DIM + qt * 128;    // == row0

    const int krow_st = tid >> 3, kcol_st = tid & 7;
    const int vrow_st = tid >> 4, vcol_st = tid & 15;

    const int kbase0 = b * S_DIM;
    {
        #pragma unroll
        for (int i = 0; i < 2; i++) {
            int row = krow_st + i * 32;
            const size_t gs = (size_t)(kbase0 + row) * D_ATT + kcol_st * 8;
            CP_ASYNC16(sb + SKBUF + row * 144 + kcol_st * 16,
                       (const char*)(g_Kh + gs));
        }
        #pragma unroll
        for (int i = 0; i < 4; i++) {
            int row = vrow_st + i * 16;
            const size_t gs = (size_t)(kbase0 + row) * D_VAL + vcol_st * 8;
            CP_ASYNC16(sb + SVBUF + row * 272 + vcol_st * 16,
                       (const char*)(g_Vh + gs));
        }
    }
    CP_COMMIT();

    // Q fragments from SQH (written by this CTA in phase 1)
    uint32_t qh[4][4];
    {
        const int rowq = wid * 16 + (lane & 15);
        const int colh = (lane >> 4) * 8;
        #pragma unroll
        for (int kk = 0; kk < 4; kk++)
            ldsm_x4(qh[kk], sb + SQH + rowq * 144 + (kk * 16 + colh) * 2);
    }

    float O[16][4];
    #pragma unroll
    for (int i = 0; i < 16; i++)
        #pragma unroll
        for (int j = 0; j < 4; j++) O[i][j] = 0.f;
    float lacc[4] = {0.f, 0.f, 0.f, 0.f};

    const int krow = lane & 7;
    const int kq   = (lane >> 3) & 3;
    const uint32_t ONE2 = 0x3C003C00u;     // (fp16 1.0, fp16 1.0)

    #pragma unroll 1
    for (int kt = 0; kt < 64; kt++) {
        const int buf = kt & 1;

        CP_WAIT(0);
        __syncthreads();

        const uint32_t kh = sb + SKBUF + buf * K_BUF_SZ;
        const uint32_t vh = sb + SVBUF + buf * V_BUF_SZ;

        // ---- S = Q K^T: 8 n-tiles of 8 keys ----
        float Sc[8][4];
        #pragma unroll
        for (int i = 0; i < 8; i++)
            #pragma unroll
            for (int j = 0; j < 4; j++) Sc[i][j] = 0.f;

        #pragma unroll
        for (int nt = 0; nt < 8; nt++) {
            #pragma unroll
            for (int kp = 0; kp < 2; kp++) {
                uint32_t a = kh + (nt * 8 + krow) * 144 + (kp * 32 + kq * 8) * 2;
                uint32_t bh[4];
                ldsm_x4(bh, a);
                mma_f16(Sc[nt], qh[2 * kp],     bh[0], bh[1]);
                mma_f16(Sc[nt], qh[2 * kp + 1], bh[2], bh[3]);
            }
        }

        // ---- mid-tile prefetch of tile kt+1 into buf^1 ----
        if (kt < 63) {
            const int kb = kbase0 + (kt + 1) * 64;
            const uint32_t dk = sb + SKBUF + (buf ^ 1) * K_BUF_SZ;
            const uint32_t dv = sb + SVBUF + (buf ^ 1) * V_BUF_SZ;
            #pragma unroll
            for (int i = 0; i < 2; i++) {
                int row = krow_st + i * 32;
                const size_t gs = (size_t)(kb + row) * D_ATT + kcol_st * 8;
                CP_ASYNC16(dk + row * 144 + kcol_st * 16,
                           (const char*)(g_Kh + gs));
            }
            #pragma unroll
            for (int i = 0; i < 4; i++) {
                int row = vrow_st + i * 16;
                const size_t gs = (size_t)(kb + row) * D_VAL + vcol_st * 8;
                CP_ASYNC16(dv + row * 272 + vcol_st * 16,
                           (const char*)(g_Vh + gs));
            }
            CP_COMMIT();
        }

        // ---- P = 2^S in packed fp16 (ex2.approx.f16x2) ----
        uint32_t Ph[4][4];
        #pragma unroll
        for (int nt = 0; nt < 8; nt++) {
            uint32_t s01 = pack_f16x2(Sc[nt][0], Sc[nt][1]);
            uint32_t s23 = pack_f16x2(Sc[nt][2], Sc[nt][3]);
            Ph[nt >> 1][(nt & 1) * 2 + 0] = ex2_f16x2(s01);
            Ph[nt >> 1][(nt & 1) * 2 + 1] = ex2_f16x2(s23);
        }

        // ---- l += P @ ones (tensor-core row sum) ----
        #pragma unroll
        for (int kk = 0; kk < 4; kk++)
            mma_f16(lacc, Ph[kk], ONE2, ONE2);

        // ---- O += P V: 16 n-tiles of 8 v-cols ----
        #pragma unroll
        for (int nt = 0; nt < 16; nt++) {
            #pragma unroll
            for (int kp = 0; kp < 2; kp++) {
                uint32_t a = vh + (kp * 32 + kq * 8 + krow) * 272 + nt * 16;
                uint32_t bh[4];
                ldsm_x4_t(bh, a);
                mma_f16(O[nt], Ph[2 * kp],     bh[0], bh[1]);
                mma_f16(O[nt], Ph[2 * kp + 1], bh[2], bh[3]);
            }
        }
    }

    // ---- epilogue: lacc holds complete row sums ----
    const float inv0 = 1.0f / lacc[0];
    const float inv1 = 1.0f / lacc[2];

    const int qa = qrow0 + wid * 16 + g;
    #pragma unroll
    for (int nt = 0; nt < 16; nt++) {
        *(float2*)(out + (size_t)qa * D_VAL + nt * 8 + 2 * t4) =
            make_float2(O[nt][0] * inv0, O[nt][1] * inv0);
        *(float2*)(out + (size_t)(qa + 8) * D_VAL + nt * 8 + 2 * t4) =
            make_float2(O[nt][2] * inv1, O[nt][3] * inv1);
    }
}

// ---------------------------------------------------------------------------
// Launch: single fused kernel (proj -> device barrier -> flash attention).
// ---------------------------------------------------------------------------
extern "C" void kernel_launch(void* const* d_in, const int* in_sizes, int n_in,
                              void* d_out, int out_size)
{
    const float* x  = (const float*)d_in[0];
    const float* Wq = (const float*)d_in[1];
    const float* Wk = (const float*)d_in[2];
    const float* Wv = (const float*)d_in[3];
    float* out = (float*)d_out;

    (void)in_sizes; (void)n_in; (void)out_size;

    cudaFuncSetAttribute(fused_kernel,
                         cudaFuncAttributeMaxDynamicSharedMemorySize,
                         SMEM_TOTAL);

    fused_kernel<<<ROWS_TOTAL / 128, 256, SMEM_TOTAL>>>(x, Wq, Wk, Wv, out);
}